// round 2
// baseline (speedup 1.0000x reference)
#include <cuda_runtime.h>

#define BATCH 512
#define NNEG  2048
#define EDIM  256
#define KDIM  512   // 2*E

// Scratch (no cudaMalloc allowed): K-major operands so GEMM loads are coalesced.
__device__ float g_At[KDIM * BATCH];   // A'[k][b]
__device__ float g_Bt[KDIM * NNEG];    // B'[k][j]
__device__ float g_c[BATCH];           // ||hh_b||^2

// ---------------------------------------------------------------------------
// Prep A: per-batch row. normalize head, gather relation, build A' columns.
// ---------------------------------------------------------------------------
__global__ void prepA_kernel(const float* __restrict__ head,
                             const float* __restrict__ rel,
                             const int* __restrict__ rid) {
    int b = blockIdx.x;
    int e = threadIdx.x;           // 0..255
    float h = head[b * EDIM + e];

    __shared__ float red[8];
    // reduce h*h over the row
    float v = h * h;
    #pragma unroll
    for (int o = 16; o > 0; o >>= 1) v += __shfl_xor_sync(0xffffffffu, v, o);
    if ((e & 31) == 0) red[e >> 5] = v;
    __syncthreads();
    float s = 0.f;
    #pragma unroll
    for (int i = 0; i < 8; i++) s += red[i];
    float norm = sqrtf(s);
    float hn = h / fmaxf(norm, 1e-12f);

    int r = rid[b];                // int32 (JAX x64 disabled downgrades int64)
    const float* rrow = rel + (size_t)r * (2 * EDIM);
    float rh = rrow[e];
    float rt = rrow[EDIM + e];
    float hh = hn * rh;

    g_At[(size_t)e * BATCH + b]          = rt * rt;
    g_At[(size_t)(EDIM + e) * BATCH + b] = -2.f * rt * hh;

    // reduce hh*hh -> c[b]
    __syncthreads();                 // red reuse
    v = hh * hh;
    #pragma unroll
    for (int o = 16; o > 0; o >>= 1) v += __shfl_xor_sync(0xffffffffu, v, o);
    if ((e & 31) == 0) red[e >> 5] = v;
    __syncthreads();
    if (e == 0) {
        float c = 0.f;
        #pragma unroll
        for (int i = 0; i < 8; i++) c += red[i];
        g_c[b] = c;
    }
}

// ---------------------------------------------------------------------------
// Prep B: per-tail row. normalize, build B' columns.
// ---------------------------------------------------------------------------
__global__ void prepB_kernel(const float* __restrict__ tail) {
    int j = blockIdx.x;
    int e = threadIdx.x;
    float t = tail[j * EDIM + e];

    __shared__ float red[8];
    float v = t * t;
    #pragma unroll
    for (int o = 16; o > 0; o >>= 1) v += __shfl_xor_sync(0xffffffffu, v, o);
    if ((e & 31) == 0) red[e >> 5] = v;
    __syncthreads();
    float s = 0.f;
    #pragma unroll
    for (int i = 0; i < 8; i++) s += red[i];
    float norm = sqrtf(s);
    float tn = t / fmaxf(norm, 1e-12f);

    g_Bt[(size_t)e * NNEG + j]          = tn * tn;
    g_Bt[(size_t)(EDIM + e) * NNEG + j] = tn;
}

// ---------------------------------------------------------------------------
// GEMM: out[b,j] = -sqrt(max(A'·B' + c[b], 0))
// 64x64 tiles, BK=32, 128 threads, 4x8 micro-tile via packed f32x2 FMA.
// ---------------------------------------------------------------------------
#define BM 64
#define BN 64
#define BK 32

__device__ __forceinline__ void ffma2(float2& d, float a, float2 b) {
    float2 a2 = make_float2(a, a);
    unsigned long long ua, ub, ud;
    ua = *reinterpret_cast<unsigned long long*>(&a2);
    ub = *reinterpret_cast<unsigned long long*>(&b);
    ud = *reinterpret_cast<unsigned long long*>(&d);
    asm("fma.rn.f32x2 %0, %1, %2, %0;" : "+l"(ud) : "l"(ua), "l"(ub));
    d = *reinterpret_cast<float2*>(&ud);
}

__global__ void __launch_bounds__(128, 2)
gemm_kernel(float* __restrict__ out) {
    __shared__ float As[BK][BM];
    __shared__ float Bs[BK][BN];

    int tid = threadIdx.x;            // 0..127
    int bn0 = blockIdx.x * BN;        // 32 tiles
    int bm0 = blockIdx.y * BM;        // 8 tiles
    int tm  = tid >> 3;               // 0..15  (4 rows each)
    int tn  = tid & 7;                // 0..7   (8 cols each)

    float2 acc[4][4];
    #pragma unroll
    for (int m = 0; m < 4; m++)
        #pragma unroll
        for (int n = 0; n < 4; n++) acc[m][n] = make_float2(0.f, 0.f);

    for (int k0 = 0; k0 < KDIM; k0 += BK) {
        // load 32x64 tiles of A' and B' (512 float4 each, 4 per thread)
        #pragma unroll
        for (int i = 0; i < 4; i++) {
            int idx = tid + i * 128;
            int kk = idx >> 4;        // 0..31
            int cc = idx & 15;        // 0..15 -> *4 floats
            *reinterpret_cast<float4*>(&As[kk][cc * 4]) =
                *reinterpret_cast<const float4*>(&g_At[(size_t)(k0 + kk) * BATCH + bm0 + cc * 4]);
            *reinterpret_cast<float4*>(&Bs[kk][cc * 4]) =
                *reinterpret_cast<const float4*>(&g_Bt[(size_t)(k0 + kk) * NNEG + bn0 + cc * 4]);
        }
        __syncthreads();

        #pragma unroll
        for (int kk = 0; kk < BK; kk++) {
            float4 a  = *reinterpret_cast<const float4*>(&As[kk][tm * 4]);
            float4 b0 = *reinterpret_cast<const float4*>(&Bs[kk][tn * 8]);
            float4 b1 = *reinterpret_cast<const float4*>(&Bs[kk][tn * 8 + 4]);
            float  av[4] = {a.x, a.y, a.z, a.w};
            float2 bv[4] = {make_float2(b0.x, b0.y), make_float2(b0.z, b0.w),
                            make_float2(b1.x, b1.y), make_float2(b1.z, b1.w)};
            #pragma unroll
            for (int m = 0; m < 4; m++)
                #pragma unroll
                for (int n = 0; n < 4; n++)
                    ffma2(acc[m][n], av[m], bv[n]);
        }
        __syncthreads();
    }

    // epilogue: add c[b], -sqrt, store 8 contiguous floats per row (2x float4)
    #pragma unroll
    for (int m = 0; m < 4; m++) {
        int gm = bm0 + tm * 4 + m;
        float c = g_c[gm];
        float4 r0, r1;
        r0.x = -sqrtf(fmaxf(acc[m][0].x + c, 0.f));
        r0.y = -sqrtf(fmaxf(acc[m][0].y + c, 0.f));
        r0.z = -sqrtf(fmaxf(acc[m][1].x + c, 0.f));
        r0.w = -sqrtf(fmaxf(acc[m][1].y + c, 0.f));
        r1.x = -sqrtf(fmaxf(acc[m][2].x + c, 0.f));
        r1.y = -sqrtf(fmaxf(acc[m][2].y + c, 0.f));
        r1.z = -sqrtf(fmaxf(acc[m][3].x + c, 0.f));
        r1.w = -sqrtf(fmaxf(acc[m][3].y + c, 0.f));
        float* o = out + (size_t)gm * NNEG + bn0 + tn * 8;
        *reinterpret_cast<float4*>(o)     = r0;
        *reinterpret_cast<float4*>(o + 4) = r1;
    }
}

// ---------------------------------------------------------------------------
extern "C" void kernel_launch(void* const* d_in, const int* in_sizes, int n_in,
                              void* d_out, int out_size) {
    const float* head = (const float*)d_in[0];       // (512, 256)
    const float* tail = (const float*)d_in[1];       // (1, 2048, 256)
    const float* rel  = (const float*)d_in[2];       // (1000, 512)
    const int*   rid  = (const int*)d_in[3];         // (512,) int32 in practice
    float* out = (float*)d_out;                      // (512, 2048)

    prepA_kernel<<<BATCH, EDIM>>>(head, rel, rid);
    prepB_kernel<<<NNEG, EDIM>>>(tail);
    dim3 grid(NNEG / BN, BATCH / BM);
    gemm_kernel<<<grid, 128>>>(out);
}

// round 3
// speedup vs baseline: 1.3947x; 1.3947x over previous
#include <cuda_runtime.h>

#define BATCH 512
#define NNEG  2048
#define EDIM  256
#define KDIM  512   // 2*E

// Row-major scratch: prep stores coalesced; GEMM transposes on smem store.
__device__ float g_A[BATCH * KDIM];   // A'[b][k]
__device__ float g_B[NNEG  * KDIM];   // B'[j][k]
__device__ float g_c[BATCH];          // ||hh_b||^2

// ---------------------------------------------------------------------------
// Fused prep: blocks [0,512) build A' + c, blocks [512,2560) build B'.
// All global stores coalesced (thread e writes column e of a row).
// ---------------------------------------------------------------------------
__global__ void prep_kernel(const float* __restrict__ head,
                            const float* __restrict__ tail,
                            const float* __restrict__ rel,
                            const int* __restrict__ rid) {
    int blk = blockIdx.x;
    int e = threadIdx.x;           // 0..255
    __shared__ float red[8];

    if (blk < BATCH) {
        int b = blk;
        float h = head[b * EDIM + e];
        float v = h * h;
        #pragma unroll
        for (int o = 16; o > 0; o >>= 1) v += __shfl_xor_sync(0xffffffffu, v, o);
        if ((e & 31) == 0) red[e >> 5] = v;
        __syncthreads();
        float s = 0.f;
        #pragma unroll
        for (int i = 0; i < 8; i++) s += red[i];
        float hn = h / fmaxf(sqrtf(s), 1e-12f);

        int r = rid[b];
        const float* rrow = rel + (size_t)r * (2 * EDIM);
        float rh = rrow[e];
        float rt = rrow[EDIM + e];
        float hh = hn * rh;

        g_A[(size_t)b * KDIM + e]        = rt * rt;
        g_A[(size_t)b * KDIM + EDIM + e] = -2.f * rt * hh;

        __syncthreads();
        v = hh * hh;
        #pragma unroll
        for (int o = 16; o > 0; o >>= 1) v += __shfl_xor_sync(0xffffffffu, v, o);
        if ((e & 31) == 0) red[e >> 5] = v;
        __syncthreads();
        if (e == 0) {
            float c = 0.f;
            #pragma unroll
            for (int i = 0; i < 8; i++) c += red[i];
            g_c[b] = c;
        }
    } else {
        int j = blk - BATCH;
        float t = tail[j * EDIM + e];
        float v = t * t;
        #pragma unroll
        for (int o = 16; o > 0; o >>= 1) v += __shfl_xor_sync(0xffffffffu, v, o);
        if ((e & 31) == 0) red[e >> 5] = v;
        __syncthreads();
        float s = 0.f;
        #pragma unroll
        for (int i = 0; i < 8; i++) s += red[i];
        float tn = t / fmaxf(sqrtf(s), 1e-12f);

        g_B[(size_t)j * KDIM + e]        = tn * tn;
        g_B[(size_t)j * KDIM + EDIM + e] = tn;
    }
}

// ---------------------------------------------------------------------------
// GEMM: out[b,j] = -sqrt(max(A'·B'^T + c[b], 0))
// 128x64 tile, BK=32, 128 threads, 8x8 micro via packed f32x2 FMA.
// Row-major global operands, transpose on smem store.
// ---------------------------------------------------------------------------
#define BM 128
#define BN 64
#define BK 32
#define NITER (KDIM / BK)   // 16

__device__ __forceinline__ void ffma2(float2& d, float a, float2 b) {
    float2 a2 = make_float2(a, a);
    unsigned long long ua = *reinterpret_cast<unsigned long long*>(&a2);
    unsigned long long ub = *reinterpret_cast<unsigned long long*>(&b);
    unsigned long long ud = *reinterpret_cast<unsigned long long*>(&d);
    asm("fma.rn.f32x2 %0, %1, %2, %0;" : "+l"(ud) : "l"(ua), "l"(ub));
    d = *reinterpret_cast<float2*>(&ud);
}

__global__ void __launch_bounds__(128, 1)
gemm_kernel(float* __restrict__ out) {
    __shared__ float As[BK][BM + 4];   // [k][m], padded
    __shared__ float Bs[BK][BN + 4];   // [k][n], padded

    int tid = threadIdx.x;             // 0..127
    int bn0 = blockIdx.x * BN;         // 32 tiles
    int bm0 = blockIdx.y * BM;         // 4 tiles
    int tm  = tid >> 3;                // 0..15 -> 8 rows each
    int tn  = tid & 7;                 // 0..7  -> 8 cols each

    float2 acc[8][4];
    #pragma unroll
    for (int m = 0; m < 8; m++)
        #pragma unroll
        for (int n = 0; n < 4; n++) acc[m][n] = make_float2(0.f, 0.f);

    // register staging for the LDG-ahead pipeline
    float4 aReg[8], bReg[4];

    // prefetch tile 0
    #pragma unroll
    for (int i = 0; i < 8; i++) {
        int idx = i * 128 + tid;
        int r = idx >> 3, kq = idx & 7;      // r:0..127, kq:0..7
        aReg[i] = *reinterpret_cast<const float4*>(&g_A[(size_t)(bm0 + r) * KDIM + kq * 4]);
    }
    #pragma unroll
    for (int i = 0; i < 4; i++) {
        int idx = i * 128 + tid;
        int r = idx >> 3, kq = idx & 7;      // r:0..63
        bReg[i] = *reinterpret_cast<const float4*>(&g_B[(size_t)(bn0 + r) * KDIM + kq * 4]);
    }

    for (int it = 0; it < NITER; it++) {
        // store staged tile to smem (transposed)
        #pragma unroll
        for (int i = 0; i < 8; i++) {
            int idx = i * 128 + tid;
            int r = idx >> 3, kq = idx & 7;
            As[kq * 4 + 0][r] = aReg[i].x;
            As[kq * 4 + 1][r] = aReg[i].y;
            As[kq * 4 + 2][r] = aReg[i].z;
            As[kq * 4 + 3][r] = aReg[i].w;
        }
        #pragma unroll
        for (int i = 0; i < 4; i++) {
            int idx = i * 128 + tid;
            int r = idx >> 3, kq = idx & 7;
            Bs[kq * 4 + 0][r] = bReg[i].x;
            Bs[kq * 4 + 1][r] = bReg[i].y;
            Bs[kq * 4 + 2][r] = bReg[i].z;
            Bs[kq * 4 + 3][r] = bReg[i].w;
        }
        __syncthreads();

        // LDG next tile while computing on current
        if (it + 1 < NITER) {
            int k0 = (it + 1) * BK;
            #pragma unroll
            for (int i = 0; i < 8; i++) {
                int idx = i * 128 + tid;
                int r = idx >> 3, kq = idx & 7;
                aReg[i] = *reinterpret_cast<const float4*>(&g_A[(size_t)(bm0 + r) * KDIM + k0 + kq * 4]);
            }
            #pragma unroll
            for (int i = 0; i < 4; i++) {
                int idx = i * 128 + tid;
                int r = idx >> 3, kq = idx & 7;
                bReg[i] = *reinterpret_cast<const float4*>(&g_B[(size_t)(bn0 + r) * KDIM + k0 + kq * 4]);
            }
        }

        #pragma unroll
        for (int kk = 0; kk < BK; kk++) {
            float4 a0 = *reinterpret_cast<const float4*>(&As[kk][tm * 8]);
            float4 a1 = *reinterpret_cast<const float4*>(&As[kk][tm * 8 + 4]);
            float4 b0 = *reinterpret_cast<const float4*>(&Bs[kk][tn * 8]);
            float4 b1 = *reinterpret_cast<const float4*>(&Bs[kk][tn * 8 + 4]);
            float  av[8] = {a0.x, a0.y, a0.z, a0.w, a1.x, a1.y, a1.z, a1.w};
            float2 bv[4] = {make_float2(b0.x, b0.y), make_float2(b0.z, b0.w),
                            make_float2(b1.x, b1.y), make_float2(b1.z, b1.w)};
            #pragma unroll
            for (int m = 0; m < 8; m++)
                #pragma unroll
                for (int n = 0; n < 4; n++)
                    ffma2(acc[m][n], av[m], bv[n]);
        }
        __syncthreads();
    }

    // epilogue: add c[b], -sqrt, 8 contiguous floats per row
    #pragma unroll
    for (int m = 0; m < 8; m++) {
        int gm = bm0 + tm * 8 + m;
        float c = g_c[gm];
        float4 r0, r1;
        r0.x = -sqrtf(fmaxf(acc[m][0].x + c, 0.f));
        r0.y = -sqrtf(fmaxf(acc[m][0].y + c, 0.f));
        r0.z = -sqrtf(fmaxf(acc[m][1].x + c, 0.f));
        r0.w = -sqrtf(fmaxf(acc[m][1].y + c, 0.f));
        r1.x = -sqrtf(fmaxf(acc[m][2].x + c, 0.f));
        r1.y = -sqrtf(fmaxf(acc[m][2].y + c, 0.f));
        r1.z = -sqrtf(fmaxf(acc[m][3].x + c, 0.f));
        r1.w = -sqrtf(fmaxf(acc[m][3].y + c, 0.f));
        float* o = out + (size_t)gm * NNEG + bn0 + tn * 8;
        *reinterpret_cast<float4*>(o)     = r0;
        *reinterpret_cast<float4*>(o + 4) = r1;
    }
}

// ---------------------------------------------------------------------------
extern "C" void kernel_launch(void* const* d_in, const int* in_sizes, int n_in,
                              void* d_out, int out_size) {
    const float* head = (const float*)d_in[0];       // (512, 256)
    const float* tail = (const float*)d_in[1];       // (1, 2048, 256)
    const float* rel  = (const float*)d_in[2];       // (1000, 512)
    const int*   rid  = (const int*)d_in[3];         // (512,) int32
    float* out = (float*)d_out;                      // (512, 2048)

    prep_kernel<<<BATCH + NNEG, EDIM>>>(head, tail, rel, rid);
    dim3 grid(NNEG / BN, BATCH / BM);
    gemm_kernel<<<grid, 128>>>(out);
}

// round 5
// speedup vs baseline: 2.5405x; 1.8215x over previous
#include <cuda_runtime.h>
#include <cuda_bf16.h>
#include <cstdint>

#define BATCH 512
#define NNEG  2048
#define EDIM  256
#define KE    1536          // 3 * 512 (hi*hi | hi*lo | lo*hi)
#define KC    64            // bf16 K per chunk (128B row)
#define NCH   (KE / KC)     // 24 chunks

// Scratch: bf16 split operands, row-major K-contiguous.
__device__ __align__(16) __nv_bfloat16 g_Abf[BATCH * KE];
__device__ __align__(16) __nv_bfloat16 g_Bbf[NNEG  * KE];
__device__ float g_c[BATCH];

__device__ __forceinline__ uint32_t s2u(const void* p) {
    uint32_t a;
    asm("{ .reg .u64 t; cvta.to.shared.u64 t, %1; cvt.u32.u64 %0, t; }" : "=r"(a) : "l"(p));
    return a;
}
__device__ __forceinline__ uint32_t sw128(uint32_t off) {
    return off ^ ((off >> 3) & 0x70);
}

// ---------------------------------------------------------------------------
// Fused prep (unchanged from R4 — compiled clean)
// ---------------------------------------------------------------------------
__device__ __forceinline__ void bsplit(float v, __nv_bfloat16& hi, __nv_bfloat16& lo) {
    hi = __float2bfloat16(v);
    lo = __float2bfloat16(v - __bfloat162float(hi));
}

__global__ void prep_kernel(const float* __restrict__ head,
                            const float* __restrict__ tail,
                            const float* __restrict__ rel,
                            const int* __restrict__ rid) {
    int blk = blockIdx.x;
    int e = threadIdx.x;           // 0..255
    __shared__ float red[8];

    if (blk < BATCH) {
        int b = blk;
        float h = head[b * EDIM + e];
        float v = h * h;
        #pragma unroll
        for (int o = 16; o > 0; o >>= 1) v += __shfl_xor_sync(0xffffffffu, v, o);
        if ((e & 31) == 0) red[e >> 5] = v;
        __syncthreads();
        float s = 0.f;
        #pragma unroll
        for (int i = 0; i < 8; i++) s += red[i];
        float hn = h / fmaxf(sqrtf(s), 1e-12f);

        int r = rid[b];
        const float* rrow = rel + (size_t)r * (2 * EDIM);
        float rh = rrow[e];
        float rt = rrow[EDIM + e];
        float hh = hn * rh;

        float v1 = rt * rt;
        float v2 = -2.f * rt * hh;
        __nv_bfloat16 h1, l1, h2, l2;
        bsplit(v1, h1, l1);
        bsplit(v2, h2, l2);
        size_t ra = (size_t)b * KE;
        g_Abf[ra + e]               = h1;   // seg0: hi   (x B hi)
        g_Abf[ra + EDIM + e]        = h2;
        g_Abf[ra + 512 + e]         = h1;   // seg1: hi   (x B lo)
        g_Abf[ra + 512 + EDIM + e]  = h2;
        g_Abf[ra + 1024 + e]        = l1;   // seg2: lo   (x B hi)
        g_Abf[ra + 1024 + EDIM + e] = l2;

        __syncthreads();
        v = hh * hh;
        #pragma unroll
        for (int o = 16; o > 0; o >>= 1) v += __shfl_xor_sync(0xffffffffu, v, o);
        if ((e & 31) == 0) red[e >> 5] = v;
        __syncthreads();
        if (e == 0) {
            float c = 0.f;
            #pragma unroll
            for (int i = 0; i < 8; i++) c += red[i];
            g_c[b] = c;
        }
    } else {
        int j = blk - BATCH;
        float t = tail[j * EDIM + e];
        float v = t * t;
        #pragma unroll
        for (int o = 16; o > 0; o >>= 1) v += __shfl_xor_sync(0xffffffffu, v, o);
        if ((e & 31) == 0) red[e >> 5] = v;
        __syncthreads();
        float s = 0.f;
        #pragma unroll
        for (int i = 0; i < 8; i++) s += red[i];
        float tn = t / fmaxf(sqrtf(s), 1e-12f);

        float w1 = tn * tn;
        float w2 = tn;
        __nv_bfloat16 h1, l1, h2, l2;
        bsplit(w1, h1, l1);
        bsplit(w2, h2, l2);
        size_t rb = (size_t)j * KE;
        g_Bbf[rb + e]               = h1;   // seg0: hi
        g_Bbf[rb + EDIM + e]        = h2;
        g_Bbf[rb + 512 + e]         = l1;   // seg1: lo
        g_Bbf[rb + 512 + EDIM + e]  = l2;
        g_Bbf[rb + 1024 + e]        = h1;   // seg2: hi
        g_Bbf[rb + 1024 + EDIM + e] = h2;
    }
}

// ---------------------------------------------------------------------------
// HMMA GEMM: 128x64 tile, 8 warps (32x32 warp tile), K=1536 in 24 chunks.
// mma.sync.m16n8k16.row.col.f32.bf16.bf16.f32, ldmatrix fragment loads.
// ---------------------------------------------------------------------------
#define BM 128
#define BN 64

__global__ void __launch_bounds__(256, 1)
gemm_mma_kernel(float* __restrict__ out) {
    __shared__ __align__(128) __nv_bfloat16 As[2][BM * KC];   // [m][k] 16KB each
    __shared__ __align__(128) __nv_bfloat16 Bs[2][BN * KC];   // [n][k] 8KB each

    int tid = threadIdx.x;             // 0..255
    int lane = tid & 31;
    int wid = tid >> 5;                // 0..7
    int wm = wid & 3;                  // 4 m-warps
    int wn = wid >> 2;                 // 2 n-warps
    int bn0 = blockIdx.x * BN;         // 32
    int bm0 = blockIdx.y * BM;         // 4

    int groupID = lane >> 2;           // 0..7
    int tig = lane & 3;                // 0..3

    float acc[2][4][4];
    #pragma unroll
    for (int mi = 0; mi < 2; mi++)
        #pragma unroll
        for (int ni = 0; ni < 4; ni++)
            #pragma unroll
            for (int q = 0; q < 4; q++) acc[mi][ni][q] = 0.f;

    uint32_t asw = s2u(&As[0][0]);
    uint32_t bsw = s2u(&Bs[0][0]);

    // ldmatrix lane-address components (byte offsets inside a tile)
    // A x4: row = lane%8 + ((lane>>3)&1)*8 ; khalf = (lane>>4)*8
    int aRow = (lane & 7) + ((lane >> 3) & 1) * 8;     // 0..15
    int aKh  = (lane >> 4) * 8;                        // 0 or 8
    // B x2: n = lane%8 ; khalf = ((lane>>3)&1)*8  (lanes 16-31 mirror 0-15)
    int bN  = lane & 7;
    int bKh = ((lane >> 3) & 1) * 8;

    // global load staging (LDG-ahead): A 4x uint4, B 2x uint4 per thread
    uint4 aReg[4], bReg[2];
    auto ldg_chunk = [&](int k0) {
        #pragma unroll
        for (int i = 0; i < 4; i++) {
            int idx = i * 256 + tid;           // 0..1023
            int r = idx >> 3, c = idx & 7;     // r:0..127
            aReg[i] = *reinterpret_cast<const uint4*>(
                &g_Abf[(size_t)(bm0 + r) * KE + k0 + c * 8]);
        }
        #pragma unroll
        for (int i = 0; i < 2; i++) {
            int idx = i * 256 + tid;           // 0..511
            int r = idx >> 3, c = idx & 7;     // r:0..63
            bReg[i] = *reinterpret_cast<const uint4*>(
                &g_Bbf[(size_t)(bn0 + r) * KE + k0 + c * 8]);
        }
    };
    auto sts_chunk = [&](int sel) {
        char* aB = reinterpret_cast<char*>(&As[sel][0]);
        char* bB = reinterpret_cast<char*>(&Bs[sel][0]);
        #pragma unroll
        for (int i = 0; i < 4; i++) {
            int idx = i * 256 + tid;
            int r = idx >> 3, c = idx & 7;
            *reinterpret_cast<uint4*>(aB + sw128(r * 128 + c * 16)) = aReg[i];
        }
        #pragma unroll
        for (int i = 0; i < 2; i++) {
            int idx = i * 256 + tid;
            int r = idx >> 3, c = idx & 7;
            *reinterpret_cast<uint4*>(bB + sw128(r * 128 + c * 16)) = bReg[i];
        }
    };

    ldg_chunk(0);
    sts_chunk(0);
    __syncthreads();

    for (int it = 0; it < NCH; it++) {
        int sel = it & 1;
        if (it + 1 < NCH) ldg_chunk((it + 1) * KC);

        uint32_t aBase = asw + sel * (BM * KC * 2);
        uint32_t bBase = bsw + sel * (BN * KC * 2);

        #pragma unroll
        for (int kk = 0; kk < 4; kk++) {       // 4 k-steps of 16
            // A fragments: 2 m-tiles
            uint32_t af[2][4];
            #pragma unroll
            for (int mi = 0; mi < 2; mi++) {
                int row = wm * 32 + mi * 16 + aRow;
                int kcol = kk * 16 + aKh;
                uint32_t addr = aBase + sw128((uint32_t)(row * 128 + kcol * 2));
                asm volatile(
                    "ldmatrix.sync.aligned.m8n8.x4.shared.b16 {%0,%1,%2,%3}, [%4];"
                    : "=r"(af[mi][0]), "=r"(af[mi][1]), "=r"(af[mi][2]), "=r"(af[mi][3])
                    : "r"(addr));
            }
            // B fragments: 4 n-tiles
            uint32_t bf[4][2];
            #pragma unroll
            for (int ni = 0; ni < 4; ni++) {
                int n = wn * 32 + ni * 8 + bN;
                int kcol = kk * 16 + bKh;
                uint32_t addr = bBase + sw128((uint32_t)(n * 128 + kcol * 2));
                asm volatile(
                    "ldmatrix.sync.aligned.m8n8.x2.shared.b16 {%0,%1}, [%2];"
                    : "=r"(bf[ni][0]), "=r"(bf[ni][1])
                    : "r"(addr));
            }
            #pragma unroll
            for (int mi = 0; mi < 2; mi++)
                #pragma unroll
                for (int ni = 0; ni < 4; ni++) {
                    asm volatile(
                        "mma.sync.aligned.m16n8k16.row.col.f32.bf16.bf16.f32 "
                        "{%0,%1,%2,%3}, {%4,%5,%6,%7}, {%8,%9}, {%0,%1,%2,%3};"
                        : "+f"(acc[mi][ni][0]), "+f"(acc[mi][ni][1]),
                          "+f"(acc[mi][ni][2]), "+f"(acc[mi][ni][3])
                        : "r"(af[mi][0]), "r"(af[mi][1]), "r"(af[mi][2]), "r"(af[mi][3]),
                          "r"(bf[ni][0]), "r"(bf[ni][1]));
                }
        }
        __syncthreads();
        if (it + 1 < NCH) {
            sts_chunk(sel ^ 1);
            __syncthreads();
        }
    }

    // epilogue: acc[mi][ni] is D[16x8] at rows wm*32+mi*16+{groupID, groupID+8},
    // cols wn*32+ni*8+tig*2 (+1). Add c[row], -sqrt, float2 stores.
    #pragma unroll
    for (int mi = 0; mi < 2; mi++) {
        int r0 = bm0 + wm * 32 + mi * 16 + groupID;
        int r1 = r0 + 8;
        float c0 = g_c[r0];
        float c1 = g_c[r1];
        #pragma unroll
        for (int ni = 0; ni < 4; ni++) {
            int col = bn0 + wn * 32 + ni * 8 + tig * 2;
            float2 v0, v1;
            v0.x = -sqrtf(fmaxf(acc[mi][ni][0] + c0, 0.f));
            v0.y = -sqrtf(fmaxf(acc[mi][ni][1] + c0, 0.f));
            v1.x = -sqrtf(fmaxf(acc[mi][ni][2] + c1, 0.f));
            v1.y = -sqrtf(fmaxf(acc[mi][ni][3] + c1, 0.f));
            *reinterpret_cast<float2*>(out + (size_t)r0 * NNEG + col) = v0;
            *reinterpret_cast<float2*>(out + (size_t)r1 * NNEG + col) = v1;
        }
    }
}

// ---------------------------------------------------------------------------
extern "C" void kernel_launch(void* const* d_in, const int* in_sizes, int n_in,
                              void* d_out, int out_size) {
    const float* head = (const float*)d_in[0];       // (512, 256)
    const float* tail = (const float*)d_in[1];       // (1, 2048, 256)
    const float* rel  = (const float*)d_in[2];       // (1000, 512)
    const int*   rid  = (const int*)d_in[3];         // (512,) int32
    float* out = (float*)d_out;                      // (512, 2048)

    prep_kernel<<<BATCH + NNEG, EDIM>>>(head, tail, rel, rid);
    dim3 grid(NNEG / BN, BATCH / BM);
    gemm_mma_kernel<<<grid, 256>>>(out);
}